// round 10
// baseline (speedup 1.0000x reference)
#include <cuda_runtime.h>
#include <cuda_bf16.h>
#include <cstdint>

#define B_     4096
#define HID_   1024
#define NHEADS 8

// ============================================================================
// PTX helpers (baseline sm_80+ features only: mma.sync / ldmatrix / cp.async)
// ============================================================================
__device__ __forceinline__ uint32_t smem_to_u32(const void* p) {
    uint32_t a;
    asm("{ .reg .u64 t; cvta.to.shared.u64 t, %1; cvt.u32.u64 %0, t; }" : "=r"(a) : "l"(p));
    return a;
}
__device__ __forceinline__ void mma16816(float* c, const uint32_t* a, const uint32_t* b) {
    asm volatile("mma.sync.aligned.m16n8k16.row.col.f32.bf16.bf16.f32 "
                 "{%0,%1,%2,%3}, {%4,%5,%6,%7}, {%8,%9}, {%0,%1,%2,%3};"
                 : "+f"(c[0]), "+f"(c[1]), "+f"(c[2]), "+f"(c[3])
                 : "r"(a[0]), "r"(a[1]), "r"(a[2]), "r"(a[3]), "r"(b[0]), "r"(b[1]));
}
__device__ __forceinline__ void ldsm_x4(uint32_t* r, uint32_t addr) {
    asm volatile("ldmatrix.sync.aligned.m8n8.x4.shared.b16 {%0,%1,%2,%3}, [%4];"
                 : "=r"(r[0]), "=r"(r[1]), "=r"(r[2]), "=r"(r[3]) : "r"(addr));
}
#define CP_ASYNC16(dst, src) \
    asm volatile("cp.async.cg.shared.global [%0], [%1], 16;" :: "r"(dst), "l"(src))
#define CP_COMMIT()  asm volatile("cp.async.commit_group;")
#define CP_WAIT_1()  asm volatile("cp.async.wait_group 1;")
#define CP_WAIT_0()  asm volatile("cp.async.wait_group 0;")

// 16B-chunk swizzle within a 64B row (4 chunks): conflict-free ldmatrix
#define SWZ(row, ch) ((ch) ^ (((row) >> 1) & 3))

// ============================================================================
// scratch (__device__ globals; allocation forbidden). 16B-aligned for cp.async.
// ============================================================================
__device__ __align__(16) __nv_bfloat16 g_encin_hi[(size_t)B_ * 1024], g_encin_lo[(size_t)B_ * 1024];
__device__ __align__(16) __nv_bfloat16 g_decin_hi[(size_t)B_ * 512],  g_decin_lo[(size_t)B_ * 512];
__device__ __align__(16) __nv_bfloat16 g_Wenc_hi[1024 * 1024],  g_Wenc_lo[1024 * 1024];   // [N,K]
__device__ __align__(16) __nv_bfloat16 g_Wdec_hi[1024 * 512],   g_Wdec_lo[1024 * 512];    // [N,K]
__device__ __align__(16) __nv_bfloat16 g_Whead_hi[(size_t)NHEADS * 1024 * 1024], g_Whead_lo[(size_t)NHEADS * 1024 * 1024];
__device__ __align__(16) __nv_bfloat16 g_ench_hi[(size_t)B_ * HID_], g_ench_lo[(size_t)B_ * HID_];
__device__ float g_dec_H[(size_t)B_ * HID_];
__device__ float g_heads[(size_t)NHEADS * B_ * HID_];
__device__ float g_spart[NHEADS * 32 * B_];      // per-(head, 32-col block) partial scores

__device__ __forceinline__ void split_bf16(float v, __nv_bfloat16& h, __nv_bfloat16& l) {
    h = __float2bfloat16(v);
    l = __float2bfloat16(v - __bfloat162float(h));
}

// ============================================================================
// activation convert: fp32 -> hi/lo bf16 planes (WHICH 0: encoder, 1: decoder)
// ============================================================================
template <int WHICH>
__global__ void convert_act(const float* __restrict__ in, int n)
{
    __nv_bfloat16* hi = (WHICH == 0) ? g_encin_hi : g_decin_hi;
    __nv_bfloat16* lo = (WHICH == 0) ? g_encin_lo : g_decin_lo;
    for (int i = blockIdx.x * blockDim.x + threadIdx.x; i < n; i += gridDim.x * blockDim.x) {
        __nv_bfloat16 h, l; split_bf16(in[i], h, l);
        hi[i] = h; lo[i] = l;
    }
}

// ============================================================================
// weight transpose+convert: fp32 [K,N] row-major -> [N,K] hi/lo bf16
// WHICH 0: W_enc (K=1024)  1: W_dec (K=512)  2: W_heads (K=1024, z=head)
// ============================================================================
template <int WHICH>
__global__ void transpose_convert(const float* __restrict__ in)
{
    const int K = (WHICH == 1) ? 512 : 1024;
    const int N = 1024;
    __nv_bfloat16* ohi = (WHICH == 0) ? g_Wenc_hi : (WHICH == 1) ? g_Wdec_hi : g_Whead_hi;
    __nv_bfloat16* olo = (WHICH == 0) ? g_Wenc_lo : (WHICH == 1) ? g_Wdec_lo : g_Whead_lo;
    const size_t moff = (size_t)blockIdx.z * K * N;
    in  += moff; ohi += moff; olo += moff;

    __shared__ float t[32][33];
    const int tx = threadIdx.x, ty = threadIdx.y;
    const int n0 = blockIdx.x * 32, k0 = blockIdx.y * 32;
#pragma unroll
    for (int j = 0; j < 32; j += 8)
        t[ty + j][tx] = in[(size_t)(k0 + ty + j) * N + n0 + tx];
    __syncthreads();
#pragma unroll
    for (int j = 0; j < 32; j += 8) {
        float v = t[tx][ty + j];                 // = in[k0+tx][n0+ty+j]
        __nv_bfloat16 h, l; split_bf16(v, h, l);
        ohi[(size_t)(n0 + ty + j) * K + k0 + tx] = h;
        olo[(size_t)(n0 + ty + j) * K + k0 + tx] = l;
    }
}

// ============================================================================
// mma.sync GEMM: 128x128 CTA tile, BK=32, 8 warps (2x4), warp tile 64x32.
// 3-stage cp.async ring, ONE __syncthreads per K-chunk.
// Split-precision bf16: acc += Ah*Bh + Ah*Bl + Al*Bh (fp32 accum).
// stage (32KB): Ah[128][32] @0 | Al @8K | Bh[128][32] @16K | Bl @24K
// MODE 0: enc (K=1024) -> g_ench hi/lo   MODE 1: dec (K=512) -> g_dec_H
// MODE 2: heads (K=1024, z=head) -> g_heads + fused score partials
// ============================================================================
template <int MODE>
__global__ void __launch_bounds__(256, 1) gemm_mma(const float* __restrict__ bias_g)
{
    constexpr int K  = (MODE == 1) ? 512 : 1024;
    constexpr int nC = K / 32;
    constexpr int STAGE = 32768;
    extern __shared__ char smem[];
    const uint32_t sbase = smem_to_u32(smem);

    const int tid  = threadIdx.x;
    const int wid  = tid >> 5, lane = tid & 31;
    const int wm   = wid >> 2, wn = wid & 3;          // 2 x 4 warp grid
    const int kh   = (MODE == 2) ? blockIdx.z : 0;
    const int rowTile = blockIdx.y * 128, colTile = blockIdx.x * 128;

    const __nv_bfloat16* Ah = ((MODE == 0) ? g_encin_hi : (MODE == 1) ? g_decin_hi : g_ench_hi)
                              + (size_t)rowTile * K;
    const __nv_bfloat16* Al = ((MODE == 0) ? g_encin_lo : (MODE == 1) ? g_decin_lo : g_ench_lo)
                              + (size_t)rowTile * K;
    const __nv_bfloat16* Bh = ((MODE == 0) ? g_Wenc_hi : (MODE == 1) ? g_Wdec_hi : g_Whead_hi)
                              + (size_t)kh * 1024 * K + (size_t)colTile * K;
    const __nv_bfloat16* Bl = ((MODE == 0) ? g_Wenc_lo : (MODE == 1) ? g_Wdec_lo : g_Whead_lo)
                              + (size_t)kh * 1024 * K + (size_t)colTile * K;
    const float* bias = bias_g + ((MODE == 2) ? kh * HID_ : 0) + colTile;

    float acc[4][4][4];
#pragma unroll
    for (int i = 0; i < 4; i++)
#pragma unroll
        for (int j = 0; j < 4; j++)
#pragma unroll
            for (int e = 0; e < 4; e++) acc[i][j][e] = 0.0f;

    // ---- stage loader: 4 planes x 512 16B-chunks, 8 chunks/thread ----
    auto load_stage = [&](int s, int k0) {
        const uint32_t st = sbase + s * STAGE;
#pragma unroll
        for (int p = 0; p < 4; p++) {
            const __nv_bfloat16* g = (p == 0 ? Ah : p == 1 ? Al : p == 2 ? Bh : Bl);
#pragma unroll
            for (int h = 0; h < 2; h++) {
                const int c = tid + h * 256;
                const int row = c >> 2, ch = c & 3;
                const uint32_t dst = st + p * 8192 + row * 64 + (SWZ(row, ch) << 4);
                const void* src = g + (size_t)row * K + k0 + ch * 8;
                CP_ASYNC16(dst, src);
            }
        }
        CP_COMMIT();
    };

    load_stage(0, 0);
    load_stage(1, 32);

    for (int c = 0; c < nC; c++) {
        if (c < nC - 1) { CP_WAIT_1(); } else { CP_WAIT_0(); }
        __syncthreads();   // stage c complete chip-wide AND all warps done with stage c-1
        if (c + 2 < nC) load_stage((c + 2) % 3, (c + 2) * 32);  // overwrites stage c-1's slot

        const uint32_t st = sbase + (c % 3) * STAGE;
#pragma unroll
        for (int kk = 0; kk < 2; kk++) {
            uint32_t aHf[4][4], aLf[4][4];
#pragma unroll
            for (int mt = 0; mt < 4; mt++) {
                const int row = wm * 64 + mt * 16 + (lane & 15);
                const int kc  = kk * 2 + (lane >> 4);
                const uint32_t off = row * 64 + (SWZ(row, kc) << 4);
                ldsm_x4(aHf[mt], st + off);
                ldsm_x4(aLf[mt], st + 8192 + off);
            }
#pragma unroll
            for (int np = 0; np < 2; np++) {       // each np covers n8 tiles 2np, 2np+1
                uint32_t bHr[4], bLr[4];
                const int rowb = wn * 32 + np * 16 + (lane & 15);
                const int kcb  = kk * 2 + (lane >> 4);
                const uint32_t offb = rowb * 64 + (SWZ(rowb, kcb) << 4);
                ldsm_x4(bHr, st + 16384 + offb);
                ldsm_x4(bLr, st + 24576 + offb);
                // frag order: {tile0_k0, tile1_k0, tile0_k1, tile1_k1}
                uint32_t bH0[2] = {bHr[0], bHr[2]}, bH1[2] = {bHr[1], bHr[3]};
                uint32_t bL0[2] = {bLr[0], bLr[2]}, bL1[2] = {bLr[1], bLr[3]};
#pragma unroll
                for (int mt = 0; mt < 4; mt++) {
                    mma16816(acc[mt][2 * np],     aHf[mt], bH0);
                    mma16816(acc[mt][2 * np],     aHf[mt], bL0);
                    mma16816(acc[mt][2 * np],     aLf[mt], bH0);
                    mma16816(acc[mt][2 * np + 1], aHf[mt], bH1);
                    mma16816(acc[mt][2 * np + 1], aHf[mt], bL1);
                    mma16816(acc[mt][2 * np + 1], aLf[mt], bH1);
                }
            }
        }
    }

    // ---- epilogue: bias + relu + store (+ fused score partials, MODE 2) ----
    const int g  = lane >> 2;          // row within m16 half
    const int cq = (lane & 3) * 2;     // col pair within n8
    float2 biasv[4];
#pragma unroll
    for (int nt = 0; nt < 4; nt++)
        biasv[nt] = *(const float2*)(bias + wn * 32 + nt * 8 + cq);

#pragma unroll
    for (int mt = 0; mt < 4; mt++) {
#pragma unroll
        for (int half = 0; half < 2; half++) {
            const int r = rowTile + wm * 64 + mt * 16 + g + half * 8;
            float rs = 0.0f;
#pragma unroll
            for (int nt = 0; nt < 4; nt++) {
                const int col = colTile + wn * 32 + nt * 8 + cq;
                float v0 = fmaxf(acc[mt][nt][half * 2 + 0] + biasv[nt].x, 0.0f);
                float v1 = fmaxf(acc[mt][nt][half * 2 + 1] + biasv[nt].y, 0.0f);
                if (MODE == 0) {
                    __nv_bfloat16 h0, l0, h1, l1;
                    split_bf16(v0, h0, l0); split_bf16(v1, h1, l1);
                    *(__nv_bfloat162*)&g_ench_hi[(size_t)r * HID_ + col] = __nv_bfloat162{h0, h1};
                    *(__nv_bfloat162*)&g_ench_lo[(size_t)r * HID_ + col] = __nv_bfloat162{l0, l1};
                } else if (MODE == 1) {
                    *(float2*)&g_dec_H[(size_t)r * HID_ + col] = make_float2(v0, v1);
                } else {
                    *(float2*)&g_heads[(size_t)kh * B_ * HID_ + (size_t)r * HID_ + col] = make_float2(v0, v1);
                    const float2 dh = *(const float2*)&g_dec_H[(size_t)r * HID_ + col];
                    rs += v0 * dh.x + v1 * dh.y;
                }
            }
            if (MODE == 2) {
                rs += __shfl_xor_sync(0xffffffffu, rs, 1);
                rs += __shfl_xor_sync(0xffffffffu, rs, 2);
                if ((lane & 3) == 0)
                    g_spart[(kh * 32 + blockIdx.x * 4 + wn) * B_ + r] = rs;  // single writer
            }
        }
    }
}

// ============================================================================
// combine (+fused softmax): contextual[b,:] = sum_k softmax_k(score) * heads[k,b,:]
// ============================================================================
__global__ void __launch_bounds__(256) combine_kernel(float* __restrict__ out)
{
    const int b = blockIdx.x;
    const int tid = threadIdx.x;
    __shared__ float red[256];
    __shared__ float sc[NHEADS];
    __shared__ float attn[NHEADS];

    {   // 8 heads x 32 col-block partials
        const int k = tid >> 5, j = tid & 31;
        red[tid] = g_spart[(k * 32 + j) * B_ + b];
    }
    __syncthreads();
    if (tid < NHEADS) {
        float s = 0.0f;
#pragma unroll
        for (int j = 0; j < 32; j++) s += red[tid * 32 + j];
        sc[tid] = s;
    }
    __syncthreads();
    if (tid == 0) {
        float m = sc[0];
#pragma unroll
        for (int k = 1; k < NHEADS; k++) m = fmaxf(m, sc[k]);
        float sum = 0.0f;
        float e[NHEADS];
#pragma unroll
        for (int k = 0; k < NHEADS; k++) { e[k] = expf(sc[k] - m); sum += e[k]; }
        const float inv = 1.0f / sum;
#pragma unroll
        for (int k = 0; k < NHEADS; k++) attn[k] = e[k] * inv;
    }
    __syncthreads();

    const int d = tid * 4;
    float4 acc = make_float4(0.f, 0.f, 0.f, 0.f);
#pragma unroll
    for (int k = 0; k < NHEADS; k++) {
        const float4 h = *(const float4*)&g_heads[((size_t)k * B_ + b) * HID_ + d];
        const float ak = attn[k];
        acc.x += ak * h.x; acc.y += ak * h.y; acc.z += ak * h.z; acc.w += ak * h.w;
    }
    *(float4*)&out[(size_t)b * HID_ + d] = acc;
}

// ============================================================================
// launch
// ============================================================================
extern "C" void kernel_launch(void* const* d_in, const int* in_sizes, int n_in,
                              void* d_out, int out_size)
{
    const float* enc_in  = (const float*)d_in[0];
    const float* dec_in  = (const float*)d_in[1];
    const float* W_enc   = (const float*)d_in[2];
    const float* b_enc   = (const float*)d_in[3];
    const float* W_heads = (const float*)d_in[4];
    const float* b_heads = (const float*)d_in[5];
    const float* W_dec   = (const float*)d_in[6];
    const float* b_dec   = (const float*)d_in[7];
    float* out = (float*)d_out;

    const int SMEM_GEMM = 3 * 32768;   // 96 KB (3-stage ring)
    static bool attr_done = false;
    if (!attr_done) {
        cudaFuncSetAttribute(gemm_mma<0>, cudaFuncAttributeMaxDynamicSharedMemorySize, SMEM_GEMM);
        cudaFuncSetAttribute(gemm_mma<1>, cudaFuncAttributeMaxDynamicSharedMemorySize, SMEM_GEMM);
        cudaFuncSetAttribute(gemm_mma<2>, cudaFuncAttributeMaxDynamicSharedMemorySize, SMEM_GEMM);
        attr_done = true;
    }

    // converts
    convert_act<0><<<1024, 256>>>(enc_in, B_ * 1024);
    convert_act<1><<<1024, 256>>>(dec_in, B_ * 512);
    transpose_convert<0><<<dim3(32, 32, 1), dim3(32, 8)>>>(W_enc);
    transpose_convert<1><<<dim3(32, 16, 1), dim3(32, 8)>>>(W_dec);
    transpose_convert<2><<<dim3(32, 32, 8), dim3(32, 8)>>>(W_heads);

    // GEMMs (mma.sync tensor cores), CTA tile 128x128
    gemm_mma<0><<<dim3(8, 32, 1), 256, SMEM_GEMM>>>(b_enc);
    gemm_mma<1><<<dim3(8, 32, 1), 256, SMEM_GEMM>>>(b_dec);
    gemm_mma<2><<<dim3(8, 32, NHEADS), 256, SMEM_GEMM>>>(b_heads);

    combine_kernel<<<B_, 256>>>(out);
}

// round 11
// speedup vs baseline: 1.3239x; 1.3239x over previous
#include <cuda_runtime.h>
#include <cuda_bf16.h>
#include <cstdint>

#define B_     4096
#define HID_   1024
#define NHEADS 8

// ============================================================================
// PTX helpers (baseline sm_80+ features only: mma.sync / ldmatrix / cp.async)
// ============================================================================
__device__ __forceinline__ uint32_t smem_to_u32(const void* p) {
    uint32_t a;
    asm("{ .reg .u64 t; cvta.to.shared.u64 t, %1; cvt.u32.u64 %0, t; }" : "=r"(a) : "l"(p));
    return a;
}
__device__ __forceinline__ void mma16816(float* c, const uint32_t* a, const uint32_t* b) {
    asm volatile("mma.sync.aligned.m16n8k16.row.col.f32.bf16.bf16.f32 "
                 "{%0,%1,%2,%3}, {%4,%5,%6,%7}, {%8,%9}, {%0,%1,%2,%3};"
                 : "+f"(c[0]), "+f"(c[1]), "+f"(c[2]), "+f"(c[3])
                 : "r"(a[0]), "r"(a[1]), "r"(a[2]), "r"(a[3]), "r"(b[0]), "r"(b[1]));
}
__device__ __forceinline__ void ldsm_x4(uint32_t* r, uint32_t addr) {
    asm volatile("ldmatrix.sync.aligned.m8n8.x4.shared.b16 {%0,%1,%2,%3}, [%4];"
                 : "=r"(r[0]), "=r"(r[1]), "=r"(r[2]), "=r"(r[3]) : "r"(addr));
}
__device__ __forceinline__ void ldsm_x2(uint32_t* r, uint32_t addr) {
    asm volatile("ldmatrix.sync.aligned.m8n8.x2.shared.b16 {%0,%1}, [%2];"
                 : "=r"(r[0]), "=r"(r[1]) : "r"(addr));
}
#define CP_ASYNC16(dst, src) \
    asm volatile("cp.async.cg.shared.global [%0], [%1], 16;" :: "r"(dst), "l"(src))
#define CP_COMMIT()  asm volatile("cp.async.commit_group;")
#define CP_WAIT_1()  asm volatile("cp.async.wait_group 1;")
#define CP_WAIT_0()  asm volatile("cp.async.wait_group 0;")

// 16B-chunk swizzle within a 64B row (4 chunks): conflict-free ldmatrix
#define SWZ(row, ch) ((ch) ^ (((row) >> 1) & 3))

// ============================================================================
// scratch (__device__ globals; allocation forbidden). 16B-aligned for cp.async.
// ============================================================================
__device__ __align__(16) __nv_bfloat16 g_encin_hi[(size_t)B_ * 1024], g_encin_lo[(size_t)B_ * 1024];
__device__ __align__(16) __nv_bfloat16 g_decin_hi[(size_t)B_ * 512],  g_decin_lo[(size_t)B_ * 512];
__device__ __align__(16) __nv_bfloat16 g_Wenc_hi[1024 * 1024],  g_Wenc_lo[1024 * 1024];   // [N,K]
__device__ __align__(16) __nv_bfloat16 g_Wdec_hi[1024 * 512],   g_Wdec_lo[1024 * 512];    // [N,K]
__device__ __align__(16) __nv_bfloat16 g_Whead_hi[(size_t)NHEADS * 1024 * 1024], g_Whead_lo[(size_t)NHEADS * 1024 * 1024];
__device__ __align__(16) __nv_bfloat16 g_ench_hi[(size_t)B_ * HID_], g_ench_lo[(size_t)B_ * HID_];
__device__ float g_dec_H[(size_t)B_ * HID_];
__device__ float g_heads[(size_t)NHEADS * B_ * HID_];
__device__ float g_spart[NHEADS * 32 * B_];      // per-(head, 32-col block) partial scores

__device__ __forceinline__ void split_bf16(float v, __nv_bfloat16& h, __nv_bfloat16& l) {
    h = __float2bfloat16(v);
    l = __float2bfloat16(v - __bfloat162float(h));
}

// ============================================================================
// activation convert: fp32 -> hi/lo bf16 planes (WHICH 0: encoder, 1: decoder)
// ============================================================================
template <int WHICH>
__global__ void convert_act(const float* __restrict__ in, int n)
{
    __nv_bfloat16* hi = (WHICH == 0) ? g_encin_hi : g_decin_hi;
    __nv_bfloat16* lo = (WHICH == 0) ? g_encin_lo : g_decin_lo;
    for (int i = blockIdx.x * blockDim.x + threadIdx.x; i < n; i += gridDim.x * blockDim.x) {
        __nv_bfloat16 h, l; split_bf16(in[i], h, l);
        hi[i] = h; lo[i] = l;
    }
}

// ============================================================================
// weight transpose+convert: fp32 [K,N] row-major -> [N,K] hi/lo bf16
// WHICH 0: W_enc (K=1024)  1: W_dec (K=512)  2: W_heads (K=1024, z=head)
// ============================================================================
template <int WHICH>
__global__ void transpose_convert(const float* __restrict__ in)
{
    const int K = (WHICH == 1) ? 512 : 1024;
    const int N = 1024;
    __nv_bfloat16* ohi = (WHICH == 0) ? g_Wenc_hi : (WHICH == 1) ? g_Wdec_hi : g_Whead_hi;
    __nv_bfloat16* olo = (WHICH == 0) ? g_Wenc_lo : (WHICH == 1) ? g_Wdec_lo : g_Whead_lo;
    const size_t moff = (size_t)blockIdx.z * K * N;
    in  += moff; ohi += moff; olo += moff;

    __shared__ float t[32][33];
    const int tx = threadIdx.x, ty = threadIdx.y;
    const int n0 = blockIdx.x * 32, k0 = blockIdx.y * 32;
#pragma unroll
    for (int j = 0; j < 32; j += 8)
        t[ty + j][tx] = in[(size_t)(k0 + ty + j) * N + n0 + tx];
    __syncthreads();
#pragma unroll
    for (int j = 0; j < 32; j += 8) {
        float v = t[tx][ty + j];                 // = in[k0+tx][n0+ty+j]
        __nv_bfloat16 h, l; split_bf16(v, h, l);
        ohi[(size_t)(n0 + ty + j) * K + k0 + tx] = h;
        olo[(size_t)(n0 + ty + j) * K + k0 + tx] = l;
    }
}

// ============================================================================
// mma.sync GEMM: 128x128 CTA tile, BK=32, 8 warps (2x4), warp tile 64x32.
// 2-stage cp.async ring; next-stage load issued BEFORE wait (overlaps issue
// with drain) — the empirically fastest mainloop structure (733us).
// Split-precision bf16: acc += Ah*Bh + Ah*Bl + Al*Bh (fp32 accum).
// stage (32KB): Ah[128][32] @0 | Al @8K | Bh[128][32] @16K | Bl @24K
// MODE 0: enc (K=1024) -> g_ench hi/lo   MODE 1: dec (K=512) -> g_dec_H
// MODE 2: heads (K=1024, z=head) -> g_heads + fused score partials
// ============================================================================
template <int MODE>
__global__ void __launch_bounds__(256) gemm_mma(const float* __restrict__ bias_g)
{
    constexpr int K  = (MODE == 1) ? 512 : 1024;
    constexpr int nC = K / 32;
    extern __shared__ char smem[];
    const uint32_t sbase = smem_to_u32(smem);

    const int tid  = threadIdx.x;
    const int wid  = tid >> 5, lane = tid & 31;
    const int wm   = wid >> 2, wn = wid & 3;          // 2 x 4 warp grid
    const int kh   = (MODE == 2) ? blockIdx.z : 0;
    const int rowTile = blockIdx.y * 128, colTile = blockIdx.x * 128;

    const __nv_bfloat16* Ah = ((MODE == 0) ? g_encin_hi : (MODE == 1) ? g_decin_hi : g_ench_hi)
                              + (size_t)rowTile * K;
    const __nv_bfloat16* Al = ((MODE == 0) ? g_encin_lo : (MODE == 1) ? g_decin_lo : g_ench_lo)
                              + (size_t)rowTile * K;
    const __nv_bfloat16* Bh = ((MODE == 0) ? g_Wenc_hi : (MODE == 1) ? g_Wdec_hi : g_Whead_hi)
                              + (size_t)kh * 1024 * K + (size_t)colTile * K;
    const __nv_bfloat16* Bl = ((MODE == 0) ? g_Wenc_lo : (MODE == 1) ? g_Wdec_lo : g_Whead_lo)
                              + (size_t)kh * 1024 * K + (size_t)colTile * K;
    const float* bias = bias_g + ((MODE == 2) ? kh * HID_ : 0) + colTile;

    float acc[4][4][4];
#pragma unroll
    for (int i = 0; i < 4; i++)
#pragma unroll
        for (int j = 0; j < 4; j++)
#pragma unroll
            for (int e = 0; e < 4; e++) acc[i][j][e] = 0.0f;

    // ---- stage loader: 4 planes x 512 16B-chunks, 8 chunks/thread ----
    auto load_stage = [&](int s, int k0) {
        const uint32_t st = sbase + s * 32768;
#pragma unroll
        for (int p = 0; p < 4; p++) {
            const __nv_bfloat16* g = (p == 0 ? Ah : p == 1 ? Al : p == 2 ? Bh : Bl);
#pragma unroll
            for (int h = 0; h < 2; h++) {
                const int c = tid + h * 256;
                const int row = c >> 2, ch = c & 3;
                const uint32_t dst = st + p * 8192 + row * 64 + (SWZ(row, ch) << 4);
                const void* src = g + (size_t)row * K + k0 + ch * 8;
                CP_ASYNC16(dst, src);
            }
        }
        CP_COMMIT();
    };

    load_stage(0, 0);

    for (int c = 0; c < nC; c++) {
        if (c + 1 < nC) { load_stage((c + 1) & 1, (c + 1) * 32); CP_WAIT_1(); }
        else            { CP_WAIT_0(); }
        __syncthreads();

        const uint32_t st = sbase + (c & 1) * 32768;
#pragma unroll
        for (int kk = 0; kk < 2; kk++) {
            uint32_t aHf[4][4], aLf[4][4], bHf[4][2], bLf[4][2];
#pragma unroll
            for (int mt = 0; mt < 4; mt++) {
                const int row = wm * 64 + mt * 16 + (lane & 15);
                const int kc  = kk * 2 + (lane >> 4);
                const uint32_t off = row * 64 + (SWZ(row, kc) << 4);
                ldsm_x4(aHf[mt], st + off);
                ldsm_x4(aLf[mt], st + 8192 + off);
            }
#pragma unroll
            for (int nt = 0; nt < 4; nt++) {
                const int rowb = wn * 32 + nt * 8 + (lane & 7);
                const int kcb  = kk * 2 + ((lane >> 3) & 1);
                const uint32_t offb = rowb * 64 + (SWZ(rowb, kcb) << 4);
                ldsm_x2(bHf[nt], st + 16384 + offb);
                ldsm_x2(bLf[nt], st + 24576 + offb);
            }
#pragma unroll
            for (int mt = 0; mt < 4; mt++)
#pragma unroll
                for (int nt = 0; nt < 4; nt++) {
                    mma16816(acc[mt][nt], aHf[mt], bHf[nt]);
                    mma16816(acc[mt][nt], aHf[mt], bLf[nt]);
                    mma16816(acc[mt][nt], aLf[mt], bHf[nt]);
                }
        }
        __syncthreads();
    }

    // ---- epilogue: bias + relu + store (+ fused score partials, MODE 2) ----
    const int g  = lane >> 2;          // row within m16 half
    const int cq = (lane & 3) * 2;     // col pair within n8
    float2 biasv[4];
#pragma unroll
    for (int nt = 0; nt < 4; nt++)
        biasv[nt] = *(const float2*)(bias + wn * 32 + nt * 8 + cq);

#pragma unroll
    for (int mt = 0; mt < 4; mt++) {
#pragma unroll
        for (int half = 0; half < 2; half++) {
            const int r = rowTile + wm * 64 + mt * 16 + g + half * 8;
            float rs = 0.0f;
#pragma unroll
            for (int nt = 0; nt < 4; nt++) {
                const int col = colTile + wn * 32 + nt * 8 + cq;
                float v0 = fmaxf(acc[mt][nt][half * 2 + 0] + biasv[nt].x, 0.0f);
                float v1 = fmaxf(acc[mt][nt][half * 2 + 1] + biasv[nt].y, 0.0f);
                if (MODE == 0) {
                    __nv_bfloat16 h0, l0, h1, l1;
                    split_bf16(v0, h0, l0); split_bf16(v1, h1, l1);
                    *(__nv_bfloat162*)&g_ench_hi[(size_t)r * HID_ + col] = __nv_bfloat162{h0, h1};
                    *(__nv_bfloat162*)&g_ench_lo[(size_t)r * HID_ + col] = __nv_bfloat162{l0, l1};
                } else if (MODE == 1) {
                    *(float2*)&g_dec_H[(size_t)r * HID_ + col] = make_float2(v0, v1);
                } else {
                    *(float2*)&g_heads[(size_t)kh * B_ * HID_ + (size_t)r * HID_ + col] = make_float2(v0, v1);
                    const float2 dh = *(const float2*)&g_dec_H[(size_t)r * HID_ + col];
                    rs += v0 * dh.x + v1 * dh.y;
                }
            }
            if (MODE == 2) {
                rs += __shfl_xor_sync(0xffffffffu, rs, 1);
                rs += __shfl_xor_sync(0xffffffffu, rs, 2);
                if ((lane & 3) == 0)
                    g_spart[(kh * 32 + blockIdx.x * 4 + wn) * B_ + r] = rs;  // single writer
            }
        }
    }
}

// ============================================================================
// combine (+fused softmax): contextual[b,:] = sum_k softmax_k(score) * heads[k,b,:]
// ============================================================================
__global__ void __launch_bounds__(256) combine_kernel(float* __restrict__ out)
{
    const int b = blockIdx.x;
    const int tid = threadIdx.x;
    __shared__ float red[256];
    __shared__ float sc[NHEADS];
    __shared__ float attn[NHEADS];

    {   // 8 heads x 32 col-block partials
        const int k = tid >> 5, j = tid & 31;
        red[tid] = g_spart[(k * 32 + j) * B_ + b];
    }
    __syncthreads();
    if (tid < NHEADS) {
        float s = 0.0f;
#pragma unroll
        for (int j = 0; j < 32; j++) s += red[tid * 32 + j];
        sc[tid] = s;
    }
    __syncthreads();
    if (tid == 0) {
        float m = sc[0];
#pragma unroll
        for (int k = 1; k < NHEADS; k++) m = fmaxf(m, sc[k]);
        float sum = 0.0f;
        float e[NHEADS];
#pragma unroll
        for (int k = 0; k < NHEADS; k++) { e[k] = expf(sc[k] - m); sum += e[k]; }
        const float inv = 1.0f / sum;
#pragma unroll
        for (int k = 0; k < NHEADS; k++) attn[k] = e[k] * inv;
    }
    __syncthreads();

    const int d = tid * 4;
    float4 acc = make_float4(0.f, 0.f, 0.f, 0.f);
#pragma unroll
    for (int k = 0; k < NHEADS; k++) {
        const float4 h = *(const float4*)&g_heads[((size_t)k * B_ + b) * HID_ + d];
        const float ak = attn[k];
        acc.x += ak * h.x; acc.y += ak * h.y; acc.z += ak * h.z; acc.w += ak * h.w;
    }
    *(float4*)&out[(size_t)b * HID_ + d] = acc;
}

// ============================================================================
// launch
// ============================================================================
extern "C" void kernel_launch(void* const* d_in, const int* in_sizes, int n_in,
                              void* d_out, int out_size)
{
    const float* enc_in  = (const float*)d_in[0];
    const float* dec_in  = (const float*)d_in[1];
    const float* W_enc   = (const float*)d_in[2];
    const float* b_enc   = (const float*)d_in[3];
    const float* W_heads = (const float*)d_in[4];
    const float* b_heads = (const float*)d_in[5];
    const float* W_dec   = (const float*)d_in[6];
    const float* b_dec   = (const float*)d_in[7];
    float* out = (float*)d_out;

    const int SMEM_GEMM = 2 * 32768;   // 64 KB (double-buffered stages)
    static bool attr_done = false;
    if (!attr_done) {
        cudaFuncSetAttribute(gemm_mma<0>, cudaFuncAttributeMaxDynamicSharedMemorySize, SMEM_GEMM);
        cudaFuncSetAttribute(gemm_mma<1>, cudaFuncAttributeMaxDynamicSharedMemorySize, SMEM_GEMM);
        cudaFuncSetAttribute(gemm_mma<2>, cudaFuncAttributeMaxDynamicSharedMemorySize, SMEM_GEMM);
        attr_done = true;
    }

    // converts
    convert_act<0><<<1024, 256>>>(enc_in, B_ * 1024);
    convert_act<1><<<1024, 256>>>(dec_in, B_ * 512);
    transpose_convert<0><<<dim3(32, 32, 1), dim3(32, 8)>>>(W_enc);
    transpose_convert<1><<<dim3(32, 16, 1), dim3(32, 8)>>>(W_dec);
    transpose_convert<2><<<dim3(32, 32, 8), dim3(32, 8)>>>(W_heads);

    // GEMMs (mma.sync tensor cores), CTA tile 128x128
    gemm_mma<0><<<dim3(8, 32, 1), 256, SMEM_GEMM>>>(b_enc);
    gemm_mma<1><<<dim3(8, 32, 1), 256, SMEM_GEMM>>>(b_dec);
    gemm_mma<2><<<dim3(8, 32, NHEADS), 256, SMEM_GEMM>>>(b_heads);

    combine_kernel<<<B_, 256>>>(out);
}

// round 14
// speedup vs baseline: 1.3276x; 1.0028x over previous
#include <cuda_runtime.h>
#include <cuda_bf16.h>
#include <cstdint>

#define B_     4096
#define HID_   1024
#define NHEADS 8

// ============================================================================
// PTX helpers (baseline sm_80+ features only: mma.sync / ldmatrix / cp.async)
// ============================================================================
__device__ __forceinline__ uint32_t smem_to_u32(const void* p) {
    uint32_t a;
    asm("{ .reg .u64 t; cvta.to.shared.u64 t, %1; cvt.u32.u64 %0, t; }" : "=r"(a) : "l"(p));
    return a;
}
__device__ __forceinline__ void mma16816(float* c, const uint32_t* a, const uint32_t* b) {
    asm volatile("mma.sync.aligned.m16n8k16.row.col.f32.bf16.bf16.f32 "
                 "{%0,%1,%2,%3}, {%4,%5,%6,%7}, {%8,%9}, {%0,%1,%2,%3};"
                 : "+f"(c[0]), "+f"(c[1]), "+f"(c[2]), "+f"(c[3])
                 : "r"(a[0]), "r"(a[1]), "r"(a[2]), "r"(a[3]), "r"(b[0]), "r"(b[1]));
}
__device__ __forceinline__ void ldsm_x4(uint32_t* r, uint32_t addr) {
    asm volatile("ldmatrix.sync.aligned.m8n8.x4.shared.b16 {%0,%1,%2,%3}, [%4];"
                 : "=r"(r[0]), "=r"(r[1]), "=r"(r[2]), "=r"(r[3]) : "r"(addr));
}
__device__ __forceinline__ void ldsm_x2(uint32_t* r, uint32_t addr) {
    asm volatile("ldmatrix.sync.aligned.m8n8.x2.shared.b16 {%0,%1}, [%2];"
                 : "=r"(r[0]), "=r"(r[1]) : "r"(addr));
}
#define CP_ASYNC16(dst, src) \
    asm volatile("cp.async.cg.shared.global [%0], [%1], 16;" :: "r"(dst), "l"(src))
#define CP_COMMIT()  asm volatile("cp.async.commit_group;")
#define CP_WAIT_1()  asm volatile("cp.async.wait_group 1;")
#define CP_WAIT_0()  asm volatile("cp.async.wait_group 0;")

// 16B-chunk swizzle within a 64B row (4 chunks): conflict-free ldmatrix
#define SWZ(row, ch) ((ch) ^ (((row) >> 1) & 3))

// ============================================================================
// scratch (__device__ globals; allocation forbidden). 16B-aligned for cp.async.
// ============================================================================
__device__ __align__(16) __nv_bfloat16 g_encin_hi[(size_t)B_ * 1024], g_encin_lo[(size_t)B_ * 1024];
__device__ __align__(16) __nv_bfloat16 g_decin_hi[(size_t)B_ * 512],  g_decin_lo[(size_t)B_ * 512];
__device__ __align__(16) __nv_bfloat16 g_Wenc_hi[1024 * 1024],  g_Wenc_lo[1024 * 1024];   // [N,K]
__device__ __align__(16) __nv_bfloat16 g_Wdec_hi[1024 * 512],   g_Wdec_lo[1024 * 512];    // [N,K]
__device__ __align__(16) __nv_bfloat16 g_Whead_hi[(size_t)NHEADS * 1024 * 1024], g_Whead_lo[(size_t)NHEADS * 1024 * 1024];
__device__ __align__(16) __nv_bfloat16 g_ench_hi[(size_t)B_ * HID_], g_ench_lo[(size_t)B_ * HID_];
__device__ float g_dec_H[(size_t)B_ * HID_];
__device__ float g_heads[(size_t)NHEADS * B_ * HID_];
__device__ float g_spart[NHEADS * 32 * B_];      // per-(head, 32-col block) partial scores

__device__ __forceinline__ void split_bf16(float v, __nv_bfloat16& h, __nv_bfloat16& l) {
    h = __float2bfloat16(v);
    l = __float2bfloat16(v - __bfloat162float(h));
}

// ============================================================================
// activation convert: fp32 -> hi/lo bf16 planes, vectorized (float2 -> bf16x2)
// WHICH 0: encoder, 1: decoder
// ============================================================================
template <int WHICH>
__global__ void convert_act(const float* __restrict__ in, int n2)  // n2 = n/2
{
    __nv_bfloat162* hi = (__nv_bfloat162*)((WHICH == 0) ? g_encin_hi : g_decin_hi);
    __nv_bfloat162* lo = (__nv_bfloat162*)((WHICH == 0) ? g_encin_lo : g_decin_lo);
    const float2* in2 = (const float2*)in;
    for (int i = blockIdx.x * blockDim.x + threadIdx.x; i < n2; i += gridDim.x * blockDim.x) {
        float2 v = in2[i];
        __nv_bfloat16 h0, l0, h1, l1;
        split_bf16(v.x, h0, l0); split_bf16(v.y, h1, l1);
        hi[i] = __nv_bfloat162{h0, h1};
        lo[i] = __nv_bfloat162{l0, l1};
    }
}

// ============================================================================
// weight transpose+convert: fp32 [K,N] row-major -> [N,K] hi/lo bf16.
// 64k x 32n tile; writes bf16x2 pairs along K (4B coalesced stores).
// WHICH 0: W_enc (K=1024)  1: W_dec (K=512)  2: W_heads (K=1024, z=head)
// ============================================================================
template <int WHICH>
__global__ void transpose_convert(const float* __restrict__ in)
{
    const int K = (WHICH == 1) ? 512 : 1024;
    const int N = 1024;
    __nv_bfloat16* ohi = (WHICH == 0) ? g_Wenc_hi : (WHICH == 1) ? g_Wdec_hi : g_Whead_hi;
    __nv_bfloat16* olo = (WHICH == 0) ? g_Wenc_lo : (WHICH == 1) ? g_Wdec_lo : g_Whead_lo;
    const size_t moff = (size_t)blockIdx.z * K * N;
    in  += moff; ohi += moff; olo += moff;

    __shared__ float t[64][33];
    const int tx = threadIdx.x, ty = threadIdx.y;   // block (32, 8)
    const int n0 = blockIdx.x * 32, k0 = blockIdx.y * 64;

    // load 64 k-rows x 32 n-cols (fp32, coalesced along n)
#pragma unroll
    for (int j = 0; j < 64; j += 8)
        t[ty + j][tx] = in[(size_t)(k0 + ty + j) * N + n0 + tx];
    __syncthreads();

    // write: thread (tx,ty) handles k-pair (k0+2tx, k0+2tx+1) for n = n0+ty+j
    // warp writes 32 consecutive bf16x2 = 128B fully coalesced
#pragma unroll
    for (int j = 0; j < 32; j += 8) {
        const int nc = ty + j;
        const float v0 = t[2 * tx][nc], v1 = t[2 * tx + 1][nc];
        __nv_bfloat16 h0, l0, h1, l1;
        split_bf16(v0, h0, l0); split_bf16(v1, h1, l1);
        const size_t off = (size_t)(n0 + nc) * K + k0 + 2 * tx;
        *(__nv_bfloat162*)&ohi[off] = __nv_bfloat162{h0, h1};
        *(__nv_bfloat162*)&olo[off] = __nv_bfloat162{l0, l1};
    }
}

// ============================================================================
// mma.sync GEMM: 128x128 CTA tile, BK=32, 8 warps (2x4), warp tile 64x32.
// 2-stage cp.async ring; next-stage load issued BEFORE wait (overlaps issue
// with drain) — the empirically fastest mainloop structure (721us).
// Split-precision bf16: acc += Ah*Bh + Ah*Bl + Al*Bh (fp32 accum).
// stage (32KB): Ah[128][32] @0 | Al @8K | Bh[128][32] @16K | Bl @24K
// MODE 0: enc (K=1024) -> g_ench hi/lo   MODE 1: dec (K=512) -> g_dec_H
// MODE 2: heads (K=1024, z=head) -> g_heads + fused score partials
// ============================================================================
template <int MODE>
__global__ void __launch_bounds__(256) gemm_mma(const float* __restrict__ bias_g)
{
    constexpr int K  = (MODE == 1) ? 512 : 1024;
    constexpr int nC = K / 32;
    extern __shared__ char smem[];
    const uint32_t sbase = smem_to_u32(smem);

    const int tid  = threadIdx.x;
    const int wid  = tid >> 5, lane = tid & 31;
    const int wm   = wid >> 2, wn = wid & 3;          // 2 x 4 warp grid
    const int kh   = (MODE == 2) ? blockIdx.z : 0;
    const int rowTile = blockIdx.y * 128, colTile = blockIdx.x * 128;

    const __nv_bfloat16* Ah = ((MODE == 0) ? g_encin_hi : (MODE == 1) ? g_decin_hi : g_ench_hi)
                              + (size_t)rowTile * K;
    const __nv_bfloat16* Al = ((MODE == 0) ? g_encin_lo : (MODE == 1) ? g_decin_lo : g_ench_lo)
                              + (size_t)rowTile * K;
    const __nv_bfloat16* Bh = ((MODE == 0) ? g_Wenc_hi : (MODE == 1) ? g_Wdec_hi : g_Whead_hi)
                              + (size_t)kh * 1024 * K + (size_t)colTile * K;
    const __nv_bfloat16* Bl = ((MODE == 0) ? g_Wenc_lo : (MODE == 1) ? g_Wdec_lo : g_Whead_lo)
                              + (size_t)kh * 1024 * K + (size_t)colTile * K;
    const float* bias = bias_g + ((MODE == 2) ? kh * HID_ : 0) + colTile;

    float acc[4][4][4];
#pragma unroll
    for (int i = 0; i < 4; i++)
#pragma unroll
        for (int j = 0; j < 4; j++)
#pragma unroll
            for (int e = 0; e < 4; e++) acc[i][j][e] = 0.0f;

    // ---- stage loader: 4 planes x 512 16B-chunks, 8 chunks/thread ----
    auto load_stage = [&](int s, int k0) {
        const uint32_t st = sbase + s * 32768;
#pragma unroll
        for (int p = 0; p < 4; p++) {
            const __nv_bfloat16* g = (p == 0 ? Ah : p == 1 ? Al : p == 2 ? Bh : Bl);
#pragma unroll
            for (int h = 0; h < 2; h++) {
                const int c = tid + h * 256;
                const int row = c >> 2, ch = c & 3;
                const uint32_t dst = st + p * 8192 + row * 64 + (SWZ(row, ch) << 4);
                const void* src = g + (size_t)row * K + k0 + ch * 8;
                CP_ASYNC16(dst, src);
            }
        }
        CP_COMMIT();
    };

    load_stage(0, 0);

    for (int c = 0; c < nC; c++) {
        if (c + 1 < nC) { load_stage((c + 1) & 1, (c + 1) * 32); CP_WAIT_1(); }
        else            { CP_WAIT_0(); }
        __syncthreads();

        const uint32_t st = sbase + (c & 1) * 32768;
#pragma unroll
        for (int kk = 0; kk < 2; kk++) {
            uint32_t aHf[4][4], aLf[4][4], bHf[4][2], bLf[4][2];
#pragma unroll
            for (int mt = 0; mt < 4; mt++) {
                const int row = wm * 64 + mt * 16 + (lane & 15);
                const int kc  = kk * 2 + (lane >> 4);
                const uint32_t off = row * 64 + (SWZ(row, kc) << 4);
                ldsm_x4(aHf[mt], st + off);
                ldsm_x4(aLf[mt], st + 8192 + off);
            }
#pragma unroll
            for (int nt = 0; nt < 4; nt++) {
                const int rowb = wn * 32 + nt * 8 + (lane & 7);
                const int kcb  = kk * 2 + ((lane >> 3) & 1);
                const uint32_t offb = rowb * 64 + (SWZ(rowb, kcb) << 4);
                ldsm_x2(bHf[nt], st + 16384 + offb);
                ldsm_x2(bLf[nt], st + 24576 + offb);
            }
#pragma unroll
            for (int mt = 0; mt < 4; mt++)
#pragma unroll
                for (int nt = 0; nt < 4; nt++) {
                    mma16816(acc[mt][nt], aHf[mt], bHf[nt]);
                    mma16816(acc[mt][nt], aHf[mt], bLf[nt]);
                    mma16816(acc[mt][nt], aLf[mt], bHf[nt]);
                }
        }
        __syncthreads();
    }

    // ---- epilogue: bias + relu + store (+ fused score partials, MODE 2) ----
    const int g  = lane >> 2;          // row within m16 half
    const int cq = (lane & 3) * 2;     // col pair within n8
    float2 biasv[4];
#pragma unroll
    for (int nt = 0; nt < 4; nt++)
        biasv[nt] = *(const float2*)(bias + wn * 32 + nt * 8 + cq);

#pragma unroll
    for (int mt = 0; mt < 4; mt++) {
#pragma unroll
        for (int half = 0; half < 2; half++) {
            const int r = rowTile + wm * 64 + mt * 16 + g + half * 8;
            float rs = 0.0f;
#pragma unroll
            for (int nt = 0; nt < 4; nt++) {
                const int col = colTile + wn * 32 + nt * 8 + cq;
                float v0 = fmaxf(acc[mt][nt][half * 2 + 0] + biasv[nt].x, 0.0f);
                float v1 = fmaxf(acc[mt][nt][half * 2 + 1] + biasv[nt].y, 0.0f);
                if (MODE == 0) {
                    __nv_bfloat16 h0, l0, h1, l1;
                    split_bf16(v0, h0, l0); split_bf16(v1, h1, l1);
                    *(__nv_bfloat162*)&g_ench_hi[(size_t)r * HID_ + col] = __nv_bfloat162{h0, h1};
                    *(__nv_bfloat162*)&g_ench_lo[(size_t)r * HID_ + col] = __nv_bfloat162{l0, l1};
                } else if (MODE == 1) {
                    *(float2*)&g_dec_H[(size_t)r * HID_ + col] = make_float2(v0, v1);
                } else {
                    *(float2*)&g_heads[(size_t)kh * B_ * HID_ + (size_t)r * HID_ + col] = make_float2(v0, v1);
                    const float2 dh = *(const float2*)&g_dec_H[(size_t)r * HID_ + col];
                    rs += v0 * dh.x + v1 * dh.y;
                }
            }
            if (MODE == 2) {
                rs += __shfl_xor_sync(0xffffffffu, rs, 1);
                rs += __shfl_xor_sync(0xffffffffu, rs, 2);
                if ((lane & 3) == 0)
                    g_spart[(kh * 32 + blockIdx.x * 4 + wn) * B_ + r] = rs;  // single writer
            }
        }
    }
}

// ============================================================================
// combine (+fused softmax): contextual[b,:] = sum_k softmax_k(score) * heads[k,b,:]
// ============================================================================
__global__ void __launch_bounds__(256) combine_kernel(float* __restrict__ out)
{
    const int b = blockIdx.x;
    const int tid = threadIdx.x;
    __shared__ float red[256];
    __shared__ float sc[NHEADS];
    __shared__ float attn[NHEADS];

    {   // 8 heads x 32 col-block partials
        const int k = tid >> 5, j = tid & 31;
        red[tid] = g_spart[(k * 32 + j) * B_ + b];
    }
    __syncthreads();
    if (tid < NHEADS) {
        float s = 0.0f;
#pragma unroll
        for (int j = 0; j < 32; j++) s += red[tid * 32 + j];
        sc[tid] = s;
    }
    __syncthreads();
    if (tid == 0) {
        float m = sc[0];
#pragma unroll
        for (int k = 1; k < NHEADS; k++) m = fmaxf(m, sc[k]);
        float sum = 0.0f;
        float e[NHEADS];
#pragma unroll
        for (int k = 0; k < NHEADS; k++) { e[k] = expf(sc[k] - m); sum += e[k]; }
        const float inv = 1.0f / sum;
#pragma unroll
        for (int k = 0; k < NHEADS; k++) attn[k] = e[k] * inv;
    }
    __syncthreads();

    const int d = tid * 4;
    float4 acc = make_float4(0.f, 0.f, 0.f, 0.f);
#pragma unroll
    for (int k = 0; k < NHEADS; k++) {
        const float4 h = *(const float4*)&g_heads[((size_t)k * B_ + b) * HID_ + d];
        const float ak = attn[k];
        acc.x += ak * h.x; acc.y += ak * h.y; acc.z += ak * h.z; acc.w += ak * h.w;
    }
    *(float4*)&out[(size_t)b * HID_ + d] = acc;
}

// ============================================================================
// launch
// ============================================================================
extern "C" void kernel_launch(void* const* d_in, const int* in_sizes, int n_in,
                              void* d_out, int out_size)
{
    const float* enc_in  = (const float*)d_in[0];
    const float* dec_in  = (const float*)d_in[1];
    const float* W_enc   = (const float*)d_in[2];
    const float* b_enc   = (const float*)d_in[3];
    const float* W_heads = (const float*)d_in[4];
    const float* b_heads = (const float*)d_in[5];
    const float* W_dec   = (const float*)d_in[6];
    const float* b_dec   = (const float*)d_in[7];
    float* out = (float*)d_out;

    const int SMEM_GEMM = 2 * 32768;   // 64 KB (double-buffered stages)
    static bool attr_done = false;
    if (!attr_done) {
        cudaFuncSetAttribute(gemm_mma<0>, cudaFuncAttributeMaxDynamicSharedMemorySize, SMEM_GEMM);
        cudaFuncSetAttribute(gemm_mma<1>, cudaFuncAttributeMaxDynamicSharedMemorySize, SMEM_GEMM);
        cudaFuncSetAttribute(gemm_mma<2>, cudaFuncAttributeMaxDynamicSharedMemorySize, SMEM_GEMM);
        attr_done = true;
    }

    // converts (vectorized)
    convert_act<0><<<512, 256>>>(enc_in, B_ * 1024 / 2);
    convert_act<1><<<512, 256>>>(dec_in, B_ * 512 / 2);
    transpose_convert<0><<<dim3(32, 16, 1), dim3(32, 8)>>>(W_enc);
    transpose_convert<1><<<dim3(32, 8, 1),  dim3(32, 8)>>>(W_dec);
    transpose_convert<2><<<dim3(32, 16, 8), dim3(32, 8)>>>(W_heads);

    // GEMMs (mma.sync tensor cores), CTA tile 128x128
    gemm_mma<0><<<dim3(8, 32, 1), 256, SMEM_GEMM>>>(b_enc);
    gemm_mma<1><<<dim3(8, 32, 1), 256, SMEM_GEMM>>>(b_dec);
    gemm_mma<2><<<dim3(8, 32, NHEADS), 256, SMEM_GEMM>>>(b_heads);

    combine_kernel<<<B_, 256>>>(out);
}

// round 16
// speedup vs baseline: 1.3441x; 1.0125x over previous
#include <cuda_runtime.h>
#include <cuda_bf16.h>
#include <cstdint>

#define B_     4096
#define HID_   1024
#define NHEADS 8

// ============================================================================
// PTX helpers (baseline sm_80+ features only: mma.sync / ldmatrix / cp.async)
// ============================================================================
__device__ __forceinline__ uint32_t smem_to_u32(const void* p) {
    uint32_t a;
    asm("{ .reg .u64 t; cvta.to.shared.u64 t, %1; cvt.u32.u64 %0, t; }" : "=r"(a) : "l"(p));
    return a;
}
__device__ __forceinline__ void mma16816(float* c, const uint32_t* a, const uint32_t* b) {
    asm volatile("mma.sync.aligned.m16n8k16.row.col.f32.bf16.bf16.f32 "
                 "{%0,%1,%2,%3}, {%4,%5,%6,%7}, {%8,%9}, {%0,%1,%2,%3};"
                 : "+f"(c[0]), "+f"(c[1]), "+f"(c[2]), "+f"(c[3])
                 : "r"(a[0]), "r"(a[1]), "r"(a[2]), "r"(a[3]), "r"(b[0]), "r"(b[1]));
}
__device__ __forceinline__ void ldsm_x4(uint32_t* r, uint32_t addr) {
    asm volatile("ldmatrix.sync.aligned.m8n8.x4.shared.b16 {%0,%1,%2,%3}, [%4];"
                 : "=r"(r[0]), "=r"(r[1]), "=r"(r[2]), "=r"(r[3]) : "r"(addr));
}
__device__ __forceinline__ void ldsm_x2(uint32_t* r, uint32_t addr) {
    asm volatile("ldmatrix.sync.aligned.m8n8.x2.shared.b16 {%0,%1}, [%2];"
                 : "=r"(r[0]), "=r"(r[1]) : "r"(addr));
}
#define CP_ASYNC16(dst, src) \
    asm volatile("cp.async.cg.shared.global [%0], [%1], 16;" :: "r"(dst), "l"(src))
#define CP_COMMIT()  asm volatile("cp.async.commit_group;")
#define CP_WAIT_1()  asm volatile("cp.async.wait_group 1;")
#define CP_WAIT_0()  asm volatile("cp.async.wait_group 0;")

// 16B-chunk swizzle within a 64B row (4 chunks): conflict-free ldmatrix
#define SWZ(row, ch) ((ch) ^ (((row) >> 1) & 3))

// ============================================================================
// scratch (__device__ globals; allocation forbidden). 16B-aligned for cp.async.
// ============================================================================
__device__ __align__(16) __nv_bfloat16 g_encin_hi[(size_t)B_ * 1024], g_encin_lo[(size_t)B_ * 1024];
__device__ __align__(16) __nv_bfloat16 g_decin_hi[(size_t)B_ * 512],  g_decin_lo[(size_t)B_ * 512];
__device__ __align__(16) __nv_bfloat16 g_Wenc_hi[1024 * 1024],  g_Wenc_lo[1024 * 1024];   // [N,K]
__device__ __align__(16) __nv_bfloat16 g_Wdec_hi[1024 * 512],   g_Wdec_lo[1024 * 512];    // [N,K]
__device__ __align__(16) __nv_bfloat16 g_Whead_hi[(size_t)NHEADS * 1024 * 1024], g_Whead_lo[(size_t)NHEADS * 1024 * 1024];
__device__ __align__(16) __nv_bfloat16 g_ench_hi[(size_t)B_ * HID_], g_ench_lo[(size_t)B_ * HID_];
__device__ float g_dec_H[(size_t)B_ * HID_];
__device__ float g_heads[(size_t)NHEADS * B_ * HID_];
__device__ float g_spart[NHEADS * 32 * B_];      // per-(head, 32-col block) partial scores

__device__ __forceinline__ void split_bf16(float v, __nv_bfloat16& h, __nv_bfloat16& l) {
    h = __float2bfloat16(v);
    l = __float2bfloat16(v - __bfloat162float(h));
}

// ============================================================================
// activation convert: fp32 -> hi/lo bf16 planes, vectorized (float2 -> bf16x2)
// WHICH 0: encoder, 1: decoder
// ============================================================================
template <int WHICH>
__global__ void convert_act(const float* __restrict__ in, int n2)  // n2 = n/2
{
    __nv_bfloat162* hi = (__nv_bfloat162*)((WHICH == 0) ? g_encin_hi : g_decin_hi);
    __nv_bfloat162* lo = (__nv_bfloat162*)((WHICH == 0) ? g_encin_lo : g_decin_lo);
    const float2* in2 = (const float2*)in;
    for (int i = blockIdx.x * blockDim.x + threadIdx.x; i < n2; i += gridDim.x * blockDim.x) {
        float2 v = in2[i];
        __nv_bfloat16 h0, l0, h1, l1;
        split_bf16(v.x, h0, l0); split_bf16(v.y, h1, l1);
        hi[i] = __nv_bfloat162{h0, h1};
        lo[i] = __nv_bfloat162{l0, l1};
    }
}

// ============================================================================
// weight transpose+convert: fp32 [K,N] row-major -> [N,K] hi/lo bf16.
// 64k x 32n tile; writes bf16x2 pairs along K (4B coalesced stores).
// WHICH 0: W_enc (K=1024)  1: W_dec (K=512)  2: W_heads (K=1024, z=head)
// ============================================================================
template <int WHICH>
__global__ void transpose_convert(const float* __restrict__ in)
{
    const int K = (WHICH == 1) ? 512 : 1024;
    const int N = 1024;
    __nv_bfloat16* ohi = (WHICH == 0) ? g_Wenc_hi : (WHICH == 1) ? g_Wdec_hi : g_Whead_hi;
    __nv_bfloat16* olo = (WHICH == 0) ? g_Wenc_lo : (WHICH == 1) ? g_Wdec_lo : g_Whead_lo;
    const size_t moff = (size_t)blockIdx.z * K * N;
    in  += moff; ohi += moff; olo += moff;

    __shared__ float t[64][33];
    const int tx = threadIdx.x, ty = threadIdx.y;   // block (32, 8)
    const int n0 = blockIdx.x * 32, k0 = blockIdx.y * 64;

    // load 64 k-rows x 32 n-cols (fp32, coalesced along n)
#pragma unroll
    for (int j = 0; j < 64; j += 8)
        t[ty + j][tx] = in[(size_t)(k0 + ty + j) * N + n0 + tx];
    __syncthreads();

    // write: thread (tx,ty) handles k-pair (k0+2tx, k0+2tx+1) for n = n0+ty+j
    // warp writes 32 consecutive bf16x2 = 128B fully coalesced
#pragma unroll
    for (int j = 0; j < 32; j += 8) {
        const int nc = ty + j;
        const float v0 = t[2 * tx][nc], v1 = t[2 * tx + 1][nc];
        __nv_bfloat16 h0, l0, h1, l1;
        split_bf16(v0, h0, l0); split_bf16(v1, h1, l1);
        const size_t off = (size_t)(n0 + nc) * K + k0 + 2 * tx;
        *(__nv_bfloat162*)&ohi[off] = __nv_bfloat162{h0, h1};
        *(__nv_bfloat162*)&olo[off] = __nv_bfloat162{l0, l1};
    }
}

// ============================================================================
// mma.sync GEMM: 128x128 CTA tile, BK=32, 8 warps (2x4), warp tile 64x32.
// 2-stage cp.async ring; next-stage load issued BEFORE wait (overlaps issue
// with drain). __launch_bounds__(256, 2): cap regs at 128 so TWO CTAs
// co-reside per SM — cross-CTA latency hiding over barriers/cp.async drains.
// Split-precision bf16: acc += Ah*Bh + Ah*Bl + Al*Bh (fp32 accum).
// stage (32KB): Ah[128][32] @0 | Al @8K | Bh[128][32] @16K | Bl @24K
// MODE 0: enc (K=1024) -> g_ench hi/lo   MODE 1: dec (K=512) -> g_dec_H
// MODE 2: heads (K=1024, z=head) -> g_heads + fused score partials
// ============================================================================
template <int MODE>
__global__ void __launch_bounds__(256, 2) gemm_mma(const float* __restrict__ bias_g)
{
    constexpr int K  = (MODE == 1) ? 512 : 1024;
    constexpr int nC = K / 32;
    extern __shared__ char smem[];
    const uint32_t sbase = smem_to_u32(smem);

    const int tid  = threadIdx.x;
    const int wid  = tid >> 5, lane = tid & 31;
    const int wm   = wid >> 2, wn = wid & 3;          // 2 x 4 warp grid
    const int kh   = (MODE == 2) ? blockIdx.z : 0;
    const int rowTile = blockIdx.y * 128, colTile = blockIdx.x * 128;

    const __nv_bfloat16* Ah = ((MODE == 0) ? g_encin_hi : (MODE == 1) ? g_decin_hi : g_ench_hi)
                              + (size_t)rowTile * K;
    const __nv_bfloat16* Al = ((MODE == 0) ? g_encin_lo : (MODE == 1) ? g_decin_lo : g_ench_lo)
                              + (size_t)rowTile * K;
    const __nv_bfloat16* Bh = ((MODE == 0) ? g_Wenc_hi : (MODE == 1) ? g_Wdec_hi : g_Whead_hi)
                              + (size_t)kh * 1024 * K + (size_t)colTile * K;
    const __nv_bfloat16* Bl = ((MODE == 0) ? g_Wenc_lo : (MODE == 1) ? g_Wdec_lo : g_Whead_lo)
                              + (size_t)kh * 1024 * K + (size_t)colTile * K;
    const float* bias = bias_g + ((MODE == 2) ? kh * HID_ : 0) + colTile;

    float acc[4][4][4];
#pragma unroll
    for (int i = 0; i < 4; i++)
#pragma unroll
        for (int j = 0; j < 4; j++)
#pragma unroll
            for (int e = 0; e < 4; e++) acc[i][j][e] = 0.0f;

    // ---- stage loader: 4 planes x 512 16B-chunks, 8 chunks/thread ----
    auto load_stage = [&](int s, int k0) {
        const uint32_t st = sbase + s * 32768;
#pragma unroll
        for (int p = 0; p < 4; p++) {
            const __nv_bfloat16* g = (p == 0 ? Ah : p == 1 ? Al : p == 2 ? Bh : Bl);
#pragma unroll
            for (int h = 0; h < 2; h++) {
                const int c = tid + h * 256;
                const int row = c >> 2, ch = c & 3;
                const uint32_t dst = st + p * 8192 + row * 64 + (SWZ(row, ch) << 4);
                const void* src = g + (size_t)row * K + k0 + ch * 8;
                CP_ASYNC16(dst, src);
            }
        }
        CP_COMMIT();
    };

    load_stage(0, 0);

    for (int c = 0; c < nC; c++) {
        if (c + 1 < nC) { load_stage((c + 1) & 1, (c + 1) * 32); CP_WAIT_1(); }
        else            { CP_WAIT_0(); }
        __syncthreads();

        const uint32_t st = sbase + (c & 1) * 32768;
#pragma unroll
        for (int kk = 0; kk < 2; kk++) {
            uint32_t aHf[4][4], aLf[4][4], bHf[4][2], bLf[4][2];
#pragma unroll
            for (int mt = 0; mt < 4; mt++) {
                const int row = wm * 64 + mt * 16 + (lane & 15);
                const int kc  = kk * 2 + (lane >> 4);
                const uint32_t off = row * 64 + (SWZ(row, kc) << 4);
                ldsm_x4(aHf[mt], st + off);
                ldsm_x4(aLf[mt], st + 8192 + off);
            }
#pragma unroll
            for (int nt = 0; nt < 4; nt++) {
                const int rowb = wn * 32 + nt * 8 + (lane & 7);
                const int kcb  = kk * 2 + ((lane >> 3) & 1);
                const uint32_t offb = rowb * 64 + (SWZ(rowb, kcb) << 4);
                ldsm_x2(bHf[nt], st + 16384 + offb);
                ldsm_x2(bLf[nt], st + 24576 + offb);
            }
#pragma unroll
            for (int mt = 0; mt < 4; mt++)
#pragma unroll
                for (int nt = 0; nt < 4; nt++) {
                    mma16816(acc[mt][nt], aHf[mt], bHf[nt]);
                    mma16816(acc[mt][nt], aHf[mt], bLf[nt]);
                    mma16816(acc[mt][nt], aLf[mt], bHf[nt]);
                }
        }
        __syncthreads();
    }

    // ---- epilogue: bias + relu + store (+ fused score partials, MODE 2) ----
    const int g  = lane >> 2;          // row within m16 half
    const int cq = (lane & 3) * 2;     // col pair within n8
    float2 biasv[4];
#pragma unroll
    for (int nt = 0; nt < 4; nt++)
        biasv[nt] = *(const float2*)(bias + wn * 32 + nt * 8 + cq);

#pragma unroll
    for (int mt = 0; mt < 4; mt++) {
#pragma unroll
        for (int half = 0; half < 2; half++) {
            const int r = rowTile + wm * 64 + mt * 16 + g + half * 8;
            float rs = 0.0f;
#pragma unroll
            for (int nt = 0; nt < 4; nt++) {
                const int col = colTile + wn * 32 + nt * 8 + cq;
                float v0 = fmaxf(acc[mt][nt][half * 2 + 0] + biasv[nt].x, 0.0f);
                float v1 = fmaxf(acc[mt][nt][half * 2 + 1] + biasv[nt].y, 0.0f);
                if (MODE == 0) {
                    __nv_bfloat16 h0, l0, h1, l1;
                    split_bf16(v0, h0, l0); split_bf16(v1, h1, l1);
                    *(__nv_bfloat162*)&g_ench_hi[(size_t)r * HID_ + col] = __nv_bfloat162{h0, h1};
                    *(__nv_bfloat162*)&g_ench_lo[(size_t)r * HID_ + col] = __nv_bfloat162{l0, l1};
                } else if (MODE == 1) {
                    *(float2*)&g_dec_H[(size_t)r * HID_ + col] = make_float2(v0, v1);
                } else {
                    *(float2*)&g_heads[(size_t)kh * B_ * HID_ + (size_t)r * HID_ + col] = make_float2(v0, v1);
                    const float2 dh = *(const float2*)&g_dec_H[(size_t)r * HID_ + col];
                    rs += v0 * dh.x + v1 * dh.y;
                }
            }
            if (MODE == 2) {
                rs += __shfl_xor_sync(0xffffffffu, rs, 1);
                rs += __shfl_xor_sync(0xffffffffu, rs, 2);
                if ((lane & 3) == 0)
                    g_spart[(kh * 32 + blockIdx.x * 4 + wn) * B_ + r] = rs;  // single writer
            }
        }
    }
}

// ============================================================================
// combine (+fused softmax): contextual[b,:] = sum_k softmax_k(score) * heads[k,b,:]
// ============================================================================
__global__ void __launch_bounds__(256) combine_kernel(float* __restrict__ out)
{
    const int b = blockIdx.x;
    const int tid = threadIdx.x;
    __shared__ float red[256];
    __shared__ float sc[NHEADS];
    __shared__ float attn[NHEADS];

    {   // 8 heads x 32 col-block partials
        const int k = tid >> 5, j = tid & 31;
        red[tid] = g_spart[(k * 32 + j) * B_ + b];
    }
    __syncthreads();
    if (tid < NHEADS) {
        float s = 0.0f;
#pragma unroll
        for (int j = 0; j < 32; j++) s += red[tid * 32 + j];
        sc[tid] = s;
    }
    __syncthreads();
    if (tid == 0) {
        float m = sc[0];
#pragma unroll
        for (int k = 1; k < NHEADS; k++) m = fmaxf(m, sc[k]);
        float sum = 0.0f;
        float e[NHEADS];
#pragma unroll
        for (int k = 0; k < NHEADS; k++) { e[k] = expf(sc[k] - m); sum += e[k]; }
        const float inv = 1.0f / sum;
#pragma unroll
        for (int k = 0; k < NHEADS; k++) attn[k] = e[k] * inv;
    }
    __syncthreads();

    const int d = tid * 4;
    float4 acc = make_float4(0.f, 0.f, 0.f, 0.f);
#pragma unroll
    for (int k = 0; k < NHEADS; k++) {
        const float4 h = *(const float4*)&g_heads[((size_t)k * B_ + b) * HID_ + d];
        const float ak = attn[k];
        acc.x += ak * h.x; acc.y += ak * h.y; acc.z += ak * h.z; acc.w += ak * h.w;
    }
    *(float4*)&out[(size_t)b * HID_ + d] = acc;
}

// ============================================================================
// launch
// ============================================================================
extern "C" void kernel_launch(void* const* d_in, const int* in_sizes, int n_in,
                              void* d_out, int out_size)
{
    const float* enc_in  = (const float*)d_in[0];
    const float* dec_in  = (const float*)d_in[1];
    const float* W_enc   = (const float*)d_in[2];
    const float* b_enc   = (const float*)d_in[3];
    const float* W_heads = (const float*)d_in[4];
    const float* b_heads = (const float*)d_in[5];
    const float* W_dec   = (const float*)d_in[6];
    const float* b_dec   = (const float*)d_in[7];
    float* out = (float*)d_out;

    const int SMEM_GEMM = 2 * 32768;   // 64 KB (double-buffered stages)
    static bool attr_done = false;
    if (!attr_done) {
        cudaFuncSetAttribute(gemm_mma<0>, cudaFuncAttributeMaxDynamicSharedMemorySize, SMEM_GEMM);
        cudaFuncSetAttribute(gemm_mma<1>, cudaFuncAttributeMaxDynamicSharedMemorySize, SMEM_GEMM);
        cudaFuncSetAttribute(gemm_mma<2>, cudaFuncAttributeMaxDynamicSharedMemorySize, SMEM_GEMM);
        attr_done = true;
    }

    // converts (vectorized)
    convert_act<0><<<512, 256>>>(enc_in, B_ * 1024 / 2);
    convert_act<1><<<512, 256>>>(dec_in, B_ * 512 / 2);
    transpose_convert<0><<<dim3(32, 16, 1), dim3(32, 8)>>>(W_enc);
    transpose_convert<1><<<dim3(32, 8, 1),  dim3(32, 8)>>>(W_dec);
    transpose_convert<2><<<dim3(32, 16, 8), dim3(32, 8)>>>(W_heads);

    // GEMMs (mma.sync tensor cores), CTA tile 128x128, 2 CTAs/SM
    gemm_mma<0><<<dim3(8, 32, 1), 256, SMEM_GEMM>>>(b_enc);
    gemm_mma<1><<<dim3(8, 32, 1), 256, SMEM_GEMM>>>(b_dec);
    gemm_mma<2><<<dim3(8, 32, NHEADS), 256, SMEM_GEMM>>>(b_heads);

    combine_kernel<<<B_, 256>>>(out);
}